// round 8
// baseline (speedup 1.0000x reference)
#include <cuda_runtime.h>

typedef unsigned int u32;
typedef unsigned long long u64;

// ---- packed f32x2 helpers (Blackwell sm_103a) ------------------------------
__device__ __forceinline__ u64 pack2(float lo, float hi) {
    u64 r; asm("mov.b64 %0, {%1, %2};" : "=l"(r) : "f"(lo), "f"(hi)); return r;
}
__device__ __forceinline__ void unpack2(u64 v, float& lo, float& hi) {
    asm("mov.b64 {%0, %1}, %2;" : "=f"(lo), "=f"(hi) : "l"(v));
}
__device__ __forceinline__ void fma2(u64& d, u64 a, u64 b, u64 c) {
    asm("fma.rn.f32x2 %0, %1, %2, %3;" : "=l"(d) : "l"(a), "l"(b), "l"(c));
}

#define H2C 2654435761u
#define H3C 805459861u

// Full weight pack in the constant bank; lower-16-cols-of-each-half come from
// const, upper-16 from smem (dual-port). One pack kernel + one memcpy node.
#define OFF_S1 0
#define OFF_S2 2048
#define OFF_C1 3072
#define OFF_C2 5120
#define OFF_C3 9216
#define W_TOTAL 9408
__constant__ __align__(16) float CW[W_TOTAL];
__device__   __align__(16) float WPACK[W_TOTAL];

__global__ void pack_weights(const float* __restrict__ s1,
                             const float* __restrict__ s2,
                             const float* __restrict__ c1,
                             const float* __restrict__ c2,
                             const float* __restrict__ c3) {
    int t = blockIdx.x * 256 + threadIdx.x;
    if (t >= W_TOTAL) return;
    float v;
    if      (t < OFF_S2) v = s1[t - OFF_S1];
    else if (t < OFF_C1) v = s2[t - OFF_S2];
    else if (t < OFF_C2) v = c1[t - OFF_C1];
    else if (t < OFF_C3) v = c2[t - OFF_C2];
    else                 v = c3[t - OFF_C3];
    WPACK[t] = v;
}

// One gather level, compile-time l. Writes 2 features.
template<int L>
__device__ __forceinline__ void do_level(float px, float py, float pz,
                                         const float* __restrict__ grids,
                                         float* encL, int slot)
{
    // res = ceil(16 * s^l), s = float32(2^0.4) (rounded up) => 65/257/1025 at l=5/10/15
    constexpr int RES_[16]  = {16,22,28,37,49,65,85,112,148,195,257,338,446,589,777,1025};
    constexpr u32 SZ_[16]   = {4096u,10648u,21952u,50656u,117656u,274632u,
                               524288u,524288u,524288u,524288u,524288u,
                               524288u,524288u,524288u,524288u,524288u};
    constexpr int R = RES_[L];
    constexpr u32 S = SZ_[L];
    const float Rf = (float)R;
    float u = px * Rf, v = py * Rf, w = pz * Rf;
    float fu = floorf(u), fv = floorf(v), fw = floorf(w);
    float fx = u - fu, fy = v - fv, fz = w - fw;
    int ix = (int)fu, iy = (int)fv, iz = (int)fw;

    u32 idx[8];
    if (L <= 2) {   // MAX_DIRECT = 2
        #pragma unroll
        for (int j = 0; j < 8; j++) {
            int cx = ix + ((j >> 2) & 1);
            int cy = iy + ((j >> 1) & 1);
            int cz = iz + (j & 1);
            idx[j] = (u32)(cz * (R * R) + cy * R + cx) % S;
        }
    } else {
        u32 hx0 = (u32)ix;           u32 hx1 = hx0 + 1u;
        u32 hy0 = (u32)iy * H2C;     u32 hy1 = hy0 + H2C;
        u32 hz0 = (u32)iz * H3C;     u32 hz1 = hz0 + H3C;
        #pragma unroll
        for (int j = 0; j < 8; j++) {
            u32 h = ((j & 4) ? hx1 : hx0) ^ ((j & 2) ? hy1 : hy0) ^ ((j & 1) ? hz1 : hz0);
            idx[j] = (L >= 6) ? (h & 524287u) : (h % S);
        }
    }

    const float2* g = (const float2*)grids + (size_t)L * 524288u;
    float2 cc[8];
    #pragma unroll
    for (int j = 0; j < 8; j++) cc[j] = __ldg(g + idx[j]);

    const float gx = 1.f - fx, gy = 1.f - fy, gz = 1.f - fz;
    float c00x = cc[0].x*gx + cc[4].x*fx, c00y = cc[0].y*gx + cc[4].y*fx;
    float c01x = cc[1].x*gx + cc[5].x*fx, c01y = cc[1].y*gx + cc[5].y*fx;
    float c10x = cc[2].x*gx + cc[6].x*fx, c10y = cc[2].y*gx + cc[6].y*fx;
    float c11x = cc[3].x*gx + cc[7].x*fx, c11y = cc[3].y*gx + cc[7].y*fx;
    float c0x = c00x*gy + c10x*fy, c0y = c00y*gy + c10y*fy;
    float c1x = c01x*gy + c11x*fy, c1y = c01y*gy + c11y*fy;
    // NOTE: replicates reference bug: c0*(1-fz) + c1*fy   (fy, not fz!)
    encL[2*slot]   = c0x*gz + c1x*fy;
    encL[2*slot+1] = c0y*gz + c1y*fy;
}

// 2 threads per point: even/odd lanes split levels (gather) and output
// columns (all GEMMs). Halved per-thread state -> 5 blocks/SM without spills.
__global__ void __launch_bounds__(128, 5) nerf_fused(
    const float* __restrict__ xin,     // (N,19)
    const float* __restrict__ grids,   // (16, 524288, 2)
    const float* __restrict__ gw_s1,   // (32,64)
    const float* __restrict__ gw_s2,   // (64,16)
    const float* __restrict__ gw_c1,   // (32,64)
    const float* __restrict__ gw_c2,   // (64,64)
    float* __restrict__ out,           // (N,4)
    int N)
{
    // smem: upper-16 columns of each 32-col half of each matrix.
    __shared__ __align__(16) ulonglong2 W1s[32 * 8];  // s1: cols 16..31 / 48..63
    __shared__ __align__(16) ulonglong2 W2s[64 * 2];  // s2: cols 8..15
    __shared__ __align__(16) ulonglong2 W3s[32 * 8];  // c1: cols 16..31 / 48..63
    __shared__ __align__(16) ulonglong2 W4s[64 * 8];  // c2: cols 16..31 / 48..63
    __shared__ float sx[64 * 19];                     // 64 points per block

    const int tid = threadIdx.x;
    {
        float* w1f = (float*)W1s;
        float* w2f = (float*)W2s;
        float* w3f = (float*)W3s;
        float* w4f = (float*)W4s;
        for (int t = tid; t < 1024; t += 128) {       // 32 rows x 32 floats
            int k = t >> 5, r = t & 31;
            int col = ((r >> 4) & 1) * 32 + 16 + (r & 15);
            w1f[t] = gw_s1[k * 64 + col];
            w3f[t] = gw_c1[k * 64 + col];
        }
        for (int t = tid; t < 512; t += 128) {        // 64 rows x 8 floats
            int m = t >> 3, e = t & 7;
            w2f[t] = gw_s2[m * 16 + 8 + e];
        }
        for (int t = tid; t < 2048; t += 128) {       // 64 rows x 32 floats
            int k = t >> 5, r = t & 31;
            int col = ((r >> 4) & 1) * 32 + 16 + (r & 15);
            w4f[t] = gw_c2[k * 64 + col];
        }
        const int base = blockIdx.x * (64 * 19);
        const int lim  = N * 19;
        #pragma unroll
        for (int t = tid; t < 64 * 19; t += 128) {
            int g = base + t;
            sx[t] = (g < lim) ? xin[g] : 0.f;
        }
    }
    __syncthreads();

    const int p = tid >> 1;                 // point slot in block
    const int h = tid & 1;                  // output-column half owned
    const int i = blockIdx.x * 64 + p;      // global point
    if (i >= N) return;
    const int laneBase = (tid & 31) & ~1;   // even lane of this pair
    const int h8 = h * 8, h4 = h * 4;

    const float px = sx[p * 19 + 0];
    const float py = sx[p * 19 + 1];
    const float pz = sx[p * 19 + 2];

    // ---- phase A: gather. Thread h does levels 8h..8h+7 -> encL[16] ---------
    float encL[16];
    if (h == 0) {
        do_level< 0>(px,py,pz,grids,encL,0); do_level< 1>(px,py,pz,grids,encL,1);
        do_level< 2>(px,py,pz,grids,encL,2); do_level< 3>(px,py,pz,grids,encL,3);
        do_level< 4>(px,py,pz,grids,encL,4); do_level< 5>(px,py,pz,grids,encL,5);
        do_level< 6>(px,py,pz,grids,encL,6); do_level< 7>(px,py,pz,grids,encL,7);
    } else {
        do_level< 8>(px,py,pz,grids,encL,0); do_level< 9>(px,py,pz,grids,encL,1);
        do_level<10>(px,py,pz,grids,encL,2); do_level<11>(px,py,pz,grids,encL,3);
        do_level<12>(px,py,pz,grids,encL,4); do_level<13>(px,py,pz,grids,encL,5);
        do_level<14>(px,py,pz,grids,encL,6); do_level<15>(px,py,pz,grids,encL,7);
    }

    // ---- gemm1 (32x64): this thread accumulates h1 cols h*32..h*32+31 ------
    // acc[q]: q<8 -> cols h*32+2q (const); q>=8 -> cols h*32+16+2(q-8) (smem)
    u64 acc[16];
    #pragma unroll
    for (int j = 0; j < 16; j++) acc[j] = 0ull;
    const ulonglong2* W1c = (const ulonglong2*)(CW + OFF_S1);  // 16 u128/row

    #pragma unroll
    for (int k = 0; k < 32; k++) {
        float ek = __shfl_sync(0xffffffffu, encL[k & 15], laneBase | (k >> 4));
        u64 a = pack2(ek, ek);
        #pragma unroll
        for (int j = 0; j < 4; j++) {
            ulonglong2 wc = W1c[k*16 + h8 + j];       // cols h*32+4j..+3
            fma2(acc[2*j],   a, wc.x, acc[2*j]);
            fma2(acc[2*j+1], a, wc.y, acc[2*j+1]);
            ulonglong2 ws = W1s[k*8 + h4 + j];        // cols h*32+16+4j..+3
            fma2(acc[8+2*j],   a, ws.x, acc[8+2*j]);
            fma2(acc[8+2*j+1], a, ws.y, acc[8+2*j+1]);
        }
    }

    // ---- relu(h1 half) folded into gemm2 (64x16) partials, then pair-reduce -
    u64 ovacc[8];
    #pragma unroll
    for (int j = 0; j < 8; j++) ovacc[j] = 0ull;
    const ulonglong2* W2c = (const ulonglong2*)(CW + OFF_S2);  // 4 u128/row

    #pragma unroll
    for (int q = 0; q < 16; q++) {
        float lo, hi; unpack2(acc[q], lo, hi);
        lo = fmaxf(lo, 0.f); hi = fmaxf(hi, 0.f);
        int m = h*32 + ((q < 8) ? 2*q : 16 + 2*(q - 8));
        u64 alo = pack2(lo, lo), ahi = pack2(hi, hi);
        #pragma unroll
        for (int j = 0; j < 2; j++) {
            ulonglong2 w0 = W2c[m*4 + j];          // out cols 4j..4j+3
            ulonglong2 w1 = W2c[(m+1)*4 + j];
            fma2(ovacc[2*j],   alo, w0.x, ovacc[2*j]);
            fma2(ovacc[2*j+1], alo, w0.y, ovacc[2*j+1]);
            fma2(ovacc[2*j],   ahi, w1.x, ovacc[2*j]);
            fma2(ovacc[2*j+1], ahi, w1.y, ovacc[2*j+1]);
            ulonglong2 s0 = W2s[m*2 + j];          // out cols 8+4j..
            ulonglong2 s1v = W2s[(m+1)*2 + j];
            fma2(ovacc[4+2*j],   alo, s0.x,  ovacc[4+2*j]);
            fma2(ovacc[4+2*j+1], alo, s0.y,  ovacc[4+2*j+1]);
            fma2(ovacc[4+2*j],   ahi, s1v.x, ovacc[4+2*j]);
            fma2(ovacc[4+2*j+1], ahi, s1v.y, ovacc[4+2*j+1]);
        }
    }
    float ov[16];
    #pragma unroll
    for (int t = 0; t < 8; t++) {
        float f0, f1; unpack2(ovacc[t], f0, f1);
        f0 += __shfl_xor_sync(0xffffffffu, f0, 1);
        f1 += __shfl_xor_sync(0xffffffffu, f1, 1);
        ov[2*t] = f0; ov[2*t+1] = f1;
    }
    const float sigma = ov[0];

    // ---- gemm3 (32x64): this thread owns hc cols h*32..+31 ------------------
    u64 acc3[16];
    #pragma unroll
    for (int j = 0; j < 16; j++) acc3[j] = 0ull;
    const ulonglong2* W3c = (const ulonglong2*)(CW + OFF_C1);

    #pragma unroll
    for (int k = 0; k < 32; k++) {
        float cik = (k < 16) ? sx[p*19 + 3 + k] : ov[k - 16];
        u64 a = pack2(cik, cik);
        #pragma unroll
        for (int j = 0; j < 4; j++) {
            ulonglong2 wc = W3c[k*16 + h8 + j];
            fma2(acc3[2*j],   a, wc.x, acc3[2*j]);
            fma2(acc3[2*j+1], a, wc.y, acc3[2*j+1]);
            ulonglong2 ws = W3s[k*8 + h4 + j];
            fma2(acc3[8+2*j],   a, ws.x, acc3[8+2*j]);
            fma2(acc3[8+2*j+1], a, ws.y, acc3[8+2*j+1]);
        }
    }
    // relu -> hcL[32]: local col lc (global col = h*32 + lc)
    float hcL[32];
    #pragma unroll
    for (int q = 0; q < 16; q++) {
        float lo, hi; unpack2(acc3[q], lo, hi);
        int lc = (q < 8) ? 2*q : 16 + 2*(q - 8);
        hcL[lc]   = fmaxf(lo, 0.f);
        hcL[lc+1] = fmaxf(hi, 0.f);
    }

    // ---- gemm4 (64x64): k streamed via pair shuffle, own 32 out cols --------
    u64 acc4[16];
    #pragma unroll
    for (int j = 0; j < 16; j++) acc4[j] = 0ull;
    const ulonglong2* W4c = (const ulonglong2*)(CW + OFF_C2);

    #pragma unroll
    for (int k = 0; k < 64; k++) {
        float hk = __shfl_sync(0xffffffffu, hcL[k & 31], laneBase | (k >> 5));
        u64 a = pack2(hk, hk);
        #pragma unroll
        for (int j = 0; j < 4; j++) {
            ulonglong2 wc = W4c[k*16 + h8 + j];
            fma2(acc4[2*j],   a, wc.x, acc4[2*j]);
            fma2(acc4[2*j+1], a, wc.y, acc4[2*j+1]);
            ulonglong2 ws = W4s[k*8 + h4 + j];
            fma2(acc4[8+2*j],   a, ws.x, acc4[8+2*j]);
            fma2(acc4[8+2*j+1], a, ws.y, acc4[8+2*j+1]);
        }
    }

    // ---- relu + gemm5 (64x3, const) partials + pair-reduce + sigmoid --------
    float col0 = 0.f, col1 = 0.f, col2 = 0.f;
    #pragma unroll
    for (int q = 0; q < 16; q++) {
        float lo, hi; unpack2(acc4[q], lo, hi);
        lo = fmaxf(lo, 0.f); hi = fmaxf(hi, 0.f);
        int c = h*32 + ((q < 8) ? 2*q : 16 + 2*(q - 8));
        col0 += lo * CW[OFF_C3 + c*3 + 0] + hi * CW[OFF_C3 + (c+1)*3 + 0];
        col1 += lo * CW[OFF_C3 + c*3 + 1] + hi * CW[OFF_C3 + (c+1)*3 + 1];
        col2 += lo * CW[OFF_C3 + c*3 + 2] + hi * CW[OFF_C3 + (c+1)*3 + 2];
    }
    col0 += __shfl_xor_sync(0xffffffffu, col0, 1);
    col1 += __shfl_xor_sync(0xffffffffu, col1, 1);
    col2 += __shfl_xor_sync(0xffffffffu, col2, 1);

    if (h == 0) {
        col0 = 1.f / (1.f + expf(-col0));
        col1 = 1.f / (1.f + expf(-col1));
        col2 = 1.f / (1.f + expf(-col2));
        float4 r; r.x = col0; r.y = col1; r.z = col2; r.w = sigma;
        ((float4*)out)[i] = r;
    }
}

extern "C" void kernel_launch(void* const* d_in, const int* in_sizes, int n_in,
                              void* d_out, int out_size) {
    const float* x     = (const float*)d_in[0];
    const float* grids = (const float*)d_in[1];
    const float* ws1   = (const float*)d_in[2];
    const float* ws2   = (const float*)d_in[3];
    const float* wc1   = (const float*)d_in[4];
    const float* wc2   = (const float*)d_in[5];
    const float* wc3   = (const float*)d_in[6];
    float* out = (float*)d_out;

    // pack all weights into one device buffer, then ONE memcpy node to const.
    pack_weights<<<(W_TOTAL + 255) / 256, 256>>>(ws1, ws2, wc1, wc2, wc3);
    void* wpack_ptr = nullptr;
    cudaGetSymbolAddress(&wpack_ptr, WPACK);
    cudaMemcpyToSymbolAsync(CW, wpack_ptr, W_TOTAL * sizeof(float), 0,
                            cudaMemcpyDeviceToDevice, 0);

    const int N = in_sizes[0] / 19;
    const int blocks = (N + 63) / 64;   // 64 points per 128-thread block
    nerf_fused<<<blocks, 128>>>(x, grids, ws1, ws2, wc1, wc2, out, N);
}

// round 9
// speedup vs baseline: 17.9053x; 17.9053x over previous
#include <cuda_runtime.h>

typedef unsigned int u32;
typedef unsigned long long u64;

// ---- packed f32x2 helpers (Blackwell sm_103a) ------------------------------
__device__ __forceinline__ u64 pack2(float lo, float hi) {
    u64 r; asm("mov.b64 %0, {%1, %2};" : "=l"(r) : "f"(lo), "f"(hi)); return r;
}
__device__ __forceinline__ void unpack2(u64 v, float& lo, float& hi) {
    asm("mov.b64 {%0, %1}, %2;" : "=f"(lo), "=f"(hi) : "l"(v));
}
__device__ __forceinline__ void fma2(u64& d, u64 a, u64 b, u64 c) {
    asm("fma.rn.f32x2 %0, %1, %2, %3;" : "=l"(d) : "l"(a), "l"(b), "l"(c));
}

#define H2C 2654435761u
#define H3C 805459861u

// Dual-port weight split (R5-proven, measured near-optimal s~0.5):
// lower 32 output cols of each matrix from the CONSTANT port (warp-uniform
// LDC only -- divergent LDC is catastrophic, R8 evidence), upper 32 cols from
// smem broadcast LDS on the L1 port. One pack kernel + ONE memcpy node.
#define OFF_S1 0
#define OFF_S2 2048
#define OFF_C1 3072
#define OFF_C2 5120
#define OFF_C3 9216
#define W_TOTAL 9408
__constant__ __align__(16) float CW[W_TOTAL];
__device__   __align__(16) float WPACK[W_TOTAL];

__global__ void pack_weights(const float* __restrict__ s1,
                             const float* __restrict__ s2,
                             const float* __restrict__ c1,
                             const float* __restrict__ c2,
                             const float* __restrict__ c3) {
    int t = blockIdx.x * 256 + threadIdx.x;
    if (t >= W_TOTAL) return;
    float v;
    if      (t < OFF_S2) v = s1[t - OFF_S1];
    else if (t < OFF_C1) v = s2[t - OFF_S2];
    else if (t < OFF_C2) v = c1[t - OFF_C1];
    else if (t < OFF_C3) v = c2[t - OFF_C2];
    else                 v = c3[t - OFF_C3];
    WPACK[t] = v;
}

// res = ceil(16 * s^l), s = float32(2^0.4) (rounded up) => 65/257/1025 at l=5/10/15.
// MAX_DIRECT = 2 (37^3, 49^3, 65^3 odd -> padded -> not direct).
__device__ __forceinline__ void level_load(int l, float px, float py, float pz,
                                           const float* __restrict__ grids,
                                           float2* cc)
{
    const int RES_[16]  = {16,22,28,37,49,65,85,112,148,195,257,338,446,589,777,1025};
    const u32 SZ_[16]   = {4096u,10648u,21952u,50656u,117656u,274632u,
                           524288u,524288u,524288u,524288u,524288u,
                           524288u,524288u,524288u,524288u,524288u};
    const int R = RES_[l];
    const u32 S = SZ_[l];
    const float Rf = (float)R;
    int ix = (int)floorf(px * Rf);
    int iy = (int)floorf(py * Rf);
    int iz = (int)floorf(pz * Rf);

    u32 idx[8];
    if (l <= 2) {
        #pragma unroll
        for (int j = 0; j < 8; j++) {
            int cx = ix + ((j >> 2) & 1);
            int cy = iy + ((j >> 1) & 1);
            int cz = iz + (j & 1);
            idx[j] = (u32)(cz * (R * R) + cy * R + cx) % S;
        }
    } else {
        u32 hx0 = (u32)ix;           u32 hx1 = hx0 + 1u;
        u32 hy0 = (u32)iy * H2C;     u32 hy1 = hy0 + H2C;
        u32 hz0 = (u32)iz * H3C;     u32 hz1 = hz0 + H3C;
        #pragma unroll
        for (int j = 0; j < 8; j++) {
            u32 h = ((j & 4) ? hx1 : hx0) ^ ((j & 2) ? hy1 : hy0) ^ ((j & 1) ? hz1 : hz0);
            idx[j] = (l >= 6) ? (h & 524287u) : (h % S);
        }
    }

    const float2* g = (const float2*)grids + (size_t)l * 524288u;
    #pragma unroll
    for (int j = 0; j < 8; j++) cc[j] = __ldg(g + idx[j]);
}

__device__ __forceinline__ void level_lerp(int l, float px, float py, float pz,
                                           const float2* cc, float* enc)
{
    const int RES_[16]  = {16,22,28,37,49,65,85,112,148,195,257,338,446,589,777,1025};
    const float Rf = (float)RES_[l];
    float u = px * Rf, v = py * Rf, w = pz * Rf;
    float fx = u - floorf(u), fy = v - floorf(v), fz = w - floorf(w);

    const float gx = 1.f - fx, gy = 1.f - fy, gz = 1.f - fz;
    float c00x = cc[0].x*gx + cc[4].x*fx, c00y = cc[0].y*gx + cc[4].y*fx;
    float c01x = cc[1].x*gx + cc[5].x*fx, c01y = cc[1].y*gx + cc[5].y*fx;
    float c10x = cc[2].x*gx + cc[6].x*fx, c10y = cc[2].y*gx + cc[6].y*fx;
    float c11x = cc[3].x*gx + cc[7].x*fx, c11y = cc[3].y*gx + cc[7].y*fx;
    float c0x = c00x*gy + c10x*fy, c0y = c00y*gy + c10y*fy;
    float c1x = c01x*gy + c11x*fy, c1y = c01y*gy + c11y*fy;
    // NOTE: replicates reference bug: c0*(1-fz) + c1*fy   (fy, not fz!)
    enc[2*l]   = c0x*gz + c1x*fy;
    enc[2*l+1] = c0y*gz + c1y*fy;
}

__global__ void __launch_bounds__(128, 4) nerf_fused(
    const float* __restrict__ xin,     // (N,19)
    const float* __restrict__ grids,   // (16, 524288, 2)
    const float* __restrict__ gw_s1,   // (32,64)
    const float* __restrict__ gw_s2,   // (64,16)
    const float* __restrict__ gw_c1,   // (32,64)
    const float* __restrict__ gw_c2,   // (64,64)
    float* __restrict__ out,           // (N,4)
    int N)
{
    __shared__ __align__(16) ulonglong2 W1s[32 * 8];  // s1 cols 32..63
    __shared__ __align__(16) ulonglong2 W2s[64 * 2];  // s2 cols  8..15
    __shared__ __align__(16) ulonglong2 W3s[32 * 8];  // c1 cols 32..63
    __shared__ __align__(16) ulonglong2 W4s[64 * 8];  // c2 cols 32..63
    __shared__ float sx[128 * 19];                    // staged xin (19 coprime 32)

    const int tid = threadIdx.x;
    {
        float* w1f = (float*)W1s;
        float* w2f = (float*)W2s;
        float* w3f = (float*)W3s;
        float* w4f = (float*)W4s;
        for (int t = tid; t < 1024; t += 128) {
            int r = t >> 5, c = t & 31;
            w1f[t] = gw_s1[r * 64 + 32 + c];
            w3f[t] = gw_c1[r * 64 + 32 + c];
        }
        for (int t = tid; t < 512; t += 128) {
            int r = t >> 3, c = t & 7;
            w2f[t] = gw_s2[r * 16 + 8 + c];
        }
        for (int t = tid; t < 2048; t += 128) {
            int r = t >> 5, c = t & 31;
            w4f[t] = gw_c2[r * 64 + 32 + c];
        }
        const int base = blockIdx.x * (128 * 19);
        const int lim  = N * 19;
        #pragma unroll
        for (int t = tid; t < 128 * 19; t += 128) {
            int g = base + t;
            sx[t] = (g < lim) ? xin[g] : 0.f;
        }
    }
    __syncthreads();

    const int i = blockIdx.x * 128 + tid;
    if (i >= N) return;

    const float px = sx[tid * 19 + 0];
    const float py = sx[tid * 19 + 1];
    const float pz = sx[tid * 19 + 2];

    // ---- phase A: gather with distance-1 prefetch (ping-pong buffers) ------
    // Level l+1's 8 LDG are in flight while level l's lerp executes, so the
    // ~300cyc L2 latency is covered by ALU/FMA work instead of stalling.
    float enc[32];
    float2 cc0[8], cc1[8];
    level_load(0, px, py, pz, grids, cc0);
    #pragma unroll
    for (int l = 0; l < 16; l += 2) {
        level_load(l + 1, px, py, pz, grids, cc1);
        level_lerp(l, px, py, pz, cc0, enc);
        if (l + 2 < 16) level_load(l + 2, px, py, pz, grids, cc0);
        level_lerp(l + 1, px, py, pz, cc1, enc);
    }

    // ---- gemm1 (32x64), dual-port, enc streamed from registers -------------
    // acc[q] = h1 cols (2q, 2q+1): q<16 from const (cols 0..31), q>=16 from
    // smem (cols 32..63). (2(q-16)+32 == 2q, so m = 2q uniformly below.)
    u64 acc[32];
    #pragma unroll
    for (int j = 0; j < 32; j++) acc[j] = 0ull;
    const ulonglong2* W1c = (const ulonglong2*)(CW + OFF_S1);  // 16 u128/row

    #pragma unroll
    for (int k = 0; k < 32; k++) {
        u64 a = pack2(enc[k], enc[k]);
        #pragma unroll
        for (int j = 0; j < 8; j++) {
            ulonglong2 wc = W1c[k*16 + j];          // cols 4j..4j+3
            fma2(acc[2*j],   a, wc.x, acc[2*j]);
            fma2(acc[2*j+1], a, wc.y, acc[2*j+1]);
            ulonglong2 ws = W1s[k*8 + j];           // cols 32+4j..+3
            fma2(acc[16+2*j],   a, ws.x, acc[16+2*j]);
            fma2(acc[16+2*j+1], a, ws.y, acc[16+2*j+1]);
        }
    }

    // ---- relu(h1) folded into gemm2 (64x16), dual-port ----------------------
    u64 ovacc[8];
    #pragma unroll
    for (int j = 0; j < 8; j++) ovacc[j] = 0ull;
    const ulonglong2* W2c = (const ulonglong2*)(CW + OFF_S2);  // 4 u128/row

    #pragma unroll
    for (int q = 0; q < 32; q++) {
        float lo, hi; unpack2(acc[q], lo, hi);
        lo = fmaxf(lo, 0.f); hi = fmaxf(hi, 0.f);
        int m = 2*q;
        u64 alo = pack2(lo, lo), ahi = pack2(hi, hi);
        #pragma unroll
        for (int j = 0; j < 2; j++) {
            ulonglong2 w0 = W2c[m*4 + j];
            ulonglong2 w1 = W2c[(m+1)*4 + j];
            fma2(ovacc[2*j],   alo, w0.x, ovacc[2*j]);
            fma2(ovacc[2*j+1], alo, w0.y, ovacc[2*j+1]);
            fma2(ovacc[2*j],   ahi, w1.x, ovacc[2*j]);
            fma2(ovacc[2*j+1], ahi, w1.y, ovacc[2*j+1]);
            ulonglong2 s0 = W2s[m*2 + j];
            ulonglong2 s1v = W2s[(m+1)*2 + j];
            fma2(ovacc[4+2*j],   alo, s0.x,  ovacc[4+2*j]);
            fma2(ovacc[4+2*j+1], alo, s0.y,  ovacc[4+2*j+1]);
            fma2(ovacc[4+2*j],   ahi, s1v.x, ovacc[4+2*j]);
            fma2(ovacc[4+2*j+1], ahi, s1v.y, ovacc[4+2*j+1]);
        }
    }
    float ov[16];
    #pragma unroll
    for (int j = 0; j < 8; j++) unpack2(ovacc[j], ov[2*j], ov[2*j+1]);
    const float sigma = ov[0];

    // ---- gemm3 (32x64), dual-port -------------------------------------------
    u64 acc3[32];
    #pragma unroll
    for (int j = 0; j < 32; j++) acc3[j] = 0ull;
    const ulonglong2* W3c = (const ulonglong2*)(CW + OFF_C1);
    const ulonglong2* W4c = (const ulonglong2*)(CW + OFF_C2);

    #pragma unroll
    for (int k = 0; k < 32; k++) {
        float cik = (k < 16) ? sx[tid*19 + 3 + k] : ov[k - 16];
        u64 a = pack2(cik, cik);
        #pragma unroll
        for (int j = 0; j < 8; j++) {
            ulonglong2 wc = W3c[k*16 + j];        // cols 4j..4j+3
            fma2(acc3[2*j],   a, wc.x, acc3[2*j]);
            fma2(acc3[2*j+1], a, wc.y, acc3[2*j+1]);
            ulonglong2 ws = W3s[k*8 + j];         // cols 32+4j..+3
            fma2(acc3[16+2*j],   a, ws.x, acc3[16+2*j]);
            fma2(acc3[16+2*j+1], a, ws.y, acc3[16+2*j+1]);
        }
    }

    // ---- relu(hc) streamed into gemm4 (64x64), dual-port --------------------
    u64 a4[32];
    #pragma unroll
    for (int j = 0; j < 32; j++) a4[j] = 0ull;
    #pragma unroll
    for (int q = 0; q < 32; q++) {
        float lo, hi; unpack2(acc3[q], lo, hi);
        lo = fmaxf(lo, 0.f); hi = fmaxf(hi, 0.f);
        int m = 2*q;
        u64 alo = pack2(lo, lo), ahi = pack2(hi, hi);
        #pragma unroll
        for (int j = 0; j < 8; j++) {
            ulonglong2 w0 = W4c[m*16 + j];
            ulonglong2 w1 = W4c[(m+1)*16 + j];
            fma2(a4[2*j],   alo, w0.x, a4[2*j]);
            fma2(a4[2*j+1], alo, w0.y, a4[2*j+1]);
            fma2(a4[2*j],   ahi, w1.x, a4[2*j]);
            fma2(a4[2*j+1], ahi, w1.y, a4[2*j+1]);
            ulonglong2 s0 = W4s[m*8 + j];
            ulonglong2 s1v = W4s[(m+1)*8 + j];
            fma2(a4[16+2*j],   alo, s0.x,  a4[16+2*j]);
            fma2(a4[16+2*j+1], alo, s0.y,  a4[16+2*j+1]);
            fma2(a4[16+2*j],   ahi, s1v.x, a4[16+2*j]);
            fma2(a4[16+2*j+1], ahi, s1v.y, a4[16+2*j+1]);
        }
    }

    // ---- relu + gemm5 (64x3, const) + sigmoid -------------------------------
    float col0 = 0.f, col1 = 0.f, col2 = 0.f;
    #pragma unroll
    for (int q = 0; q < 32; q++) {
        float lo, hi; unpack2(a4[q], lo, hi);
        lo = fmaxf(lo, 0.f); hi = fmaxf(hi, 0.f);
        int m = 2*q;
        col0 += lo * CW[OFF_C3 + m*3 + 0] + hi * CW[OFF_C3 + (m+1)*3 + 0];
        col1 += lo * CW[OFF_C3 + m*3 + 1] + hi * CW[OFF_C3 + (m+1)*3 + 1];
        col2 += lo * CW[OFF_C3 + m*3 + 2] + hi * CW[OFF_C3 + (m+1)*3 + 2];
    }

    col0 = 1.f / (1.f + expf(-col0));
    col1 = 1.f / (1.f + expf(-col1));
    col2 = 1.f / (1.f + expf(-col2));

    float4 r; r.x = col0; r.y = col1; r.z = col2; r.w = sigma;
    ((float4*)out)[i] = r;
}

extern "C" void kernel_launch(void* const* d_in, const int* in_sizes, int n_in,
                              void* d_out, int out_size) {
    const float* x     = (const float*)d_in[0];
    const float* grids = (const float*)d_in[1];
    const float* ws1   = (const float*)d_in[2];
    const float* ws2   = (const float*)d_in[3];
    const float* wc1   = (const float*)d_in[4];
    const float* wc2   = (const float*)d_in[5];
    const float* wc3   = (const float*)d_in[6];
    float* out = (float*)d_out;

    // pack all weights into one device buffer, then ONE memcpy node to const.
    pack_weights<<<(W_TOTAL + 255) / 256, 256>>>(ws1, ws2, wc1, wc2, wc3);
    void* wpack_ptr = nullptr;
    cudaGetSymbolAddress(&wpack_ptr, WPACK);
    cudaMemcpyToSymbolAsync(CW, wpack_ptr, W_TOTAL * sizeof(float), 0,
                            cudaMemcpyDeviceToDevice, 0);

    const int N = in_sizes[0] / 19;
    const int blocks = (N + 127) / 128;
    nerf_fused<<<blocks, 128>>>(x, grids, ws1, ws2, wc1, wc2, out, N);
}